// round 14
// baseline (speedup 1.0000x reference)
#include <cuda_runtime.h>
#include <cuda_bf16.h>
#include <cstdint>

#define DI __device__ __forceinline__

// Problem shape (fixed by the dataset)
static constexpr int M_TOTAL = 8192;   // B*S = 4*2048
static constexpr int N_TOTAL = 4096;
static constexpr int K_TOTAL = 1024;

// bf16 scratch (harness promotes int8 jax arrays to int32 buffers; int8 values
// are exact in bf16, fp32 accumulation exact: |acc| <= 127*127*1024 < 2^24)
__device__ __align__(16) uint16_t g_xh[(size_t)M_TOTAL * K_TOTAL];   // 16 MB
__device__ __align__(16) uint16_t g_wh[(size_t)N_TOTAL * K_TOTAL];   // 8 MB

// Tiling: CTA tile 128x128, 8 warps (4M x 2N), warp tile 32x64.
// PERSISTENT: 296 CTAs (2/SM), each walks ~7 tiles with a flat chunk counter
// so the cp.async pipeline never drains across tile boundaries (next tile's
// first stages load during this tile's last MMAs + epilogue).
static constexpr int TILE_M  = 128;
static constexpr int TILE_N  = 128;
static constexpr int KSTAGE  = 64;                   // K elems per chunk (128 B/row)
static constexpr int NCHUNK  = K_TOTAL / KSTAGE;     // 16 chunks per tile
static constexpr int NSTAGES = 3;
static constexpr int THREADS = 256;                  // 8 warps
static constexpr int GRID    = 296;                  // 2 per SM x 148 SMs
static constexpr int NTILES  = (M_TOTAL / TILE_M) * (N_TOTAL / TILE_N);  // 2048
static constexpr int GRID_NX = N_TOTAL / TILE_N;     // 32 (n fast => L2 locality)

// SMEM: bf16 tiles, rows padded 128B -> 144B (9x16B stride => conflict-free ldmatrix)
static constexpr int ROW_B   = 144;
static constexpr int A_STAGE = TILE_M * ROW_B;       // 18432 B
static constexpr int B_STAGE = TILE_N * ROW_B;       // 18432 B
static constexpr int SM_B0   = NSTAGES * A_STAGE;
static constexpr int SM_BYTES = NSTAGES * (A_STAGE + B_STAGE);  // 110592 B (x2 <= 228K)

DI uint32_t smem_u32(const void* p) {
    uint32_t a;
    asm("{ .reg .u64 t; cvta.to.shared.u64 t, %1; cvt.u32.u64 %0, t; }" : "=r"(a) : "l"(p));
    return a;
}
DI void cp16(uint32_t dst, const void* src) {
    asm volatile("cp.async.cg.shared.global [%0], [%1], 16;" :: "r"(dst), "l"(src));
}
#define CP_COMMIT() asm volatile("cp.async.commit_group;" ::: "memory")
#define CP_WAIT1()  asm volatile("cp.async.wait_group 1;" ::: "memory")

DI void ldsm4(uint32_t* r, uint32_t addr) {
    asm volatile("ldmatrix.sync.aligned.m8n8.x4.shared.b16 {%0,%1,%2,%3}, [%4];"
                 : "=r"(r[0]), "=r"(r[1]), "=r"(r[2]), "=r"(r[3]) : "r"(addr));
}
DI void mma_bf16(float* c, const uint32_t* a, uint32_t b0, uint32_t b1) {
    asm volatile(
        "mma.sync.aligned.m16n8k16.row.col.f32.bf16.bf16.f32 "
        "{%0,%1,%2,%3}, {%4,%5,%6,%7}, {%8,%9}, {%0,%1,%2,%3};"
        : "+f"(c[0]), "+f"(c[1]), "+f"(c[2]), "+f"(c[3])
        : "r"(a[0]), "r"(a[1]), "r"(a[2]), "r"(a[3]), "r"(b0), "r"(b1));
}

// ---------------- Pack pre-pass: int32 -> bf16, 8 elements/thread ----------------
DI uint32_t bf16x2_from_ints(int lo, int hi) {
    uint32_t r;
    asm("cvt.rn.bf16x2.f32 %0, %1, %2;" : "=r"(r) : "f"((float)hi), "f"((float)lo));
    return r;
}
DI uint4 pack8(const int4* p) {
    int4 v0 = p[0], v1 = p[1];
    uint4 o;
    o.x = bf16x2_from_ints(v0.x, v0.y);
    o.y = bf16x2_from_ints(v0.z, v0.w);
    o.z = bf16x2_from_ints(v1.x, v1.y);
    o.w = bf16x2_from_ints(v1.z, v1.w);
    return o;
}
__global__ void pack_both(const int4* __restrict__ xs, const int4* __restrict__ ws,
                          uint16_t* __restrict__ xd, uint16_t* __restrict__ wd,
                          int n8x, int n8w) {
    int i = blockIdx.x * blockDim.x + threadIdx.x;
    if (i < n8w) {
        reinterpret_cast<uint4*>(wd)[i] = pack8(ws + (size_t)i * 2);
    } else if (i - n8w < n8x) {
        int j = i - n8w;
        reinterpret_cast<uint4*>(xd)[j] = pack8(xs + (size_t)j * 2);
    }
}

// Load global chunk c for this CTA: tile = bid + (c/16)*GRID, kc = c&15.
// A 128 rows + B 128 rows, 128B/row, via cp.async (4+4 per thread).
DI void load_chunk(const uint16_t* __restrict__ x, const uint16_t* __restrict__ w,
                   int bid, int c, uint32_t sbase, int tid) {
    const int tile = bid + (c >> 4) * GRID;
    const int kc   = c & (NCHUNK - 1);
    const int m0 = (tile / GRID_NX) * TILE_M;
    const int n0 = (tile % GRID_NX) * TILE_N;
    const int stage = c % NSTAGES;
    const uint32_t smA = sbase + stage * A_STAGE;
    const uint32_t smB = sbase + SM_B0 + stage * B_STAGE;
    const int k0 = kc * KSTAGE;
#pragma unroll
    for (int i = 0; i < 4; i++) {                    // A: 1024 16B-chunks, 4/thread
        int u = tid + i * THREADS;
        int row = u >> 3, cc = u & 7;
        cp16(smA + row * ROW_B + cc * 16, x + (size_t)(m0 + row) * K_TOTAL + k0 + cc * 8);
    }
#pragma unroll
    for (int i = 0; i < 4; i++) {                    // B: 1024 16B-chunks, 4/thread
        int u = tid + i * THREADS;
        int row = u >> 3, cc = u & 7;
        cp16(smB + row * ROW_B + cc * 16, w + (size_t)(n0 + row) * K_TOTAL + k0 + cc * 8);
    }
}

__global__ void __launch_bounds__(THREADS, 2)
qgemm_hmma_kernel(const float* __restrict__ scale_i, const float* __restrict__ scale_w,
                  const float* __restrict__ bias, float* __restrict__ out) {
    extern __shared__ char smem[];
    const uint16_t* __restrict__ x = g_xh;
    const uint16_t* __restrict__ w = g_wh;
    const uint32_t sbase = smem_u32(smem);
    const int tid = threadIdx.x;
    const int lane = tid & 31;
    const int wid = tid >> 5;
    const int bid = blockIdx.x;
    const int warp_m = wid & 3;        // 4 warps along M: 32 rows each
    const int warp_n = wid >> 2;       // 2 warps along N: 64 cols each

    const int tg = lane >> 2;          // groupID (0..7)
    const int tc = lane & 3;           // threadID_in_group

    // Tiles for this CTA: bid, bid+GRID, ...  (first 272 CTAs get 7, rest 6)
    const int ntiles = (NTILES - bid + GRID - 1) / GRID;
    const int total_c = ntiles * NCHUNK;

    float acc[2][8][4];
#pragma unroll
    for (int mt = 0; mt < 2; mt++)
#pragma unroll
        for (int nt = 0; nt < 8; nt++)
#pragma unroll
            for (int j = 0; j < 4; j++) acc[mt][nt][j] = 0.0f;

    // ldmatrix lane addressing (within a stage):
    // A x4: [rows 0-7, k0-7][rows 8-15, k0-7][rows 0-7, k8-15][rows 8-15, k8-15]
    const int am = lane >> 3;
    const uint32_t aOff = (uint32_t)(warp_m * 32 + (am & 1) * 8 + (lane & 7)) * ROW_B
                        + (uint32_t)(am >> 1) * 16;
    // B x4 per n-tile pair p: [n 0-7, k0-7][n 0-7, k8-15][n 8-15, k0-7][n 8-15, k8-15]
    const uint32_t bOff = (uint32_t)(warp_n * 64 + (am >> 1) * 8 + (lane & 7)) * ROW_B
                        + (uint32_t)(am & 1) * 16;

    const float si = __ldg(scale_i);

    // Prologue: chunks 0,1 in flight
    load_chunk(x, w, bid, 0, sbase, tid); CP_COMMIT();
    load_chunk(x, w, bid, 1, sbase, tid); CP_COMMIT();

#pragma unroll 1
    for (int c = 0; c < total_c; c++) {
        CP_WAIT1();                    // chunk c resident
        __syncthreads();               // all warps done reading buf (c+2)%3's old data
        if (c + 2 < total_c)
            load_chunk(x, w, bid, c + 2, sbase, tid);
        CP_COMMIT();

        const int stage = c % NSTAGES;
        const uint32_t aS = sbase + stage * A_STAGE + aOff;
        const uint32_t bS = sbase + SM_B0 + stage * B_STAGE + bOff;
#pragma unroll
        for (int ks = 0; ks < 4; ks++) {           // four k=16 steps per chunk
            const uint32_t ko = ks * 32;           // 16 bf16 = 32 bytes
            uint32_t a[2][4];
            ldsm4(a[0], aS + ko);
            ldsm4(a[1], aS + 16 * ROW_B + ko);
#pragma unroll
            for (int p = 0; p < 4; p++) {          // n-tile pairs (2p, 2p+1)
                uint32_t b[4];
                ldsm4(b, bS + (uint32_t)p * 16 * ROW_B + ko);
                mma_bf16(acc[0][2 * p + 0], a[0], b[0], b[1]);
                mma_bf16(acc[1][2 * p + 0], a[1], b[0], b[1]);
                mma_bf16(acc[0][2 * p + 1], a[0], b[2], b[3]);
                mma_bf16(acc[1][2 * p + 1], a[1], b[2], b[3]);
            }
        }

        // Tile finished? Epilogue overlaps with next tile's in-flight loads.
        if ((c & (NCHUNK - 1)) == (NCHUNK - 1)) {
            const int tile = bid + (c >> 4) * GRID;
            const int m0 = (tile / GRID_NX) * TILE_M;
            const int n0 = (tile % GRID_NX) * TILE_N;
            const int row0 = m0 + warp_m * 32 + tg;
            const int col0 = n0 + warp_n * 64 + tc * 2;
#pragma unroll
            for (int nt = 0; nt < 8; nt++) {
                const int cc = col0 + nt * 8;
                const float2 sw = __ldg(reinterpret_cast<const float2*>(scale_w + cc));
                const float2 bb = __ldg(reinterpret_cast<const float2*>(bias + cc));
                const float s0 = si * sw.x, s1 = si * sw.y;
#pragma unroll
                for (int mt = 0; mt < 2; mt++) {
                    const int r = row0 + mt * 16;
                    float2 v0, v1;
                    v0.x = fmaf(acc[mt][nt][0], s0, bb.x);
                    v0.y = fmaf(acc[mt][nt][1], s1, bb.y);
                    v1.x = fmaf(acc[mt][nt][2], s0, bb.x);
                    v1.y = fmaf(acc[mt][nt][3], s1, bb.y);
                    *reinterpret_cast<float2*>(out + (size_t)r * N_TOTAL + cc)       = v0;
                    *reinterpret_cast<float2*>(out + (size_t)(r + 8) * N_TOTAL + cc) = v1;
                }
            }
#pragma unroll
            for (int mt = 0; mt < 2; mt++)
#pragma unroll
                for (int nt = 0; nt < 8; nt++)
#pragma unroll
                    for (int j = 0; j < 4; j++) acc[mt][nt][j] = 0.0f;
        }
    }
}

extern "C" void kernel_launch(void* const* d_in, const int* in_sizes, int n_in,
                              void* d_out, int out_size) {
    // Harness promotes int8 jax arrays to int32 buffers.
    const int4* x32 = (const int4*)d_in[0];      // [8192,1024] int32 (int8 values)
    const int4* w32 = (const int4*)d_in[1];      // [4096,1024] int32
    const float* si = (const float*)d_in[2];     // scalar f32
    const float* sw = (const float*)d_in[3];     // [4096] f32
    const float* bi = (const float*)d_in[4];     // [4096] f32
    float* out = (float*)d_out;                  // [8192,4096] f32

    uint16_t *dxh = nullptr, *dwh = nullptr;
    cudaGetSymbolAddress((void**)&dxh, g_xh);
    cudaGetSymbolAddress((void**)&dwh, g_wh);

    {
        int n8x = (M_TOTAL * K_TOTAL) / 8;       // 1048576
        int n8w = (N_TOTAL * K_TOTAL) / 8;       // 524288
        int total = n8x + n8w;
        pack_both<<<(total + 255) / 256, 256>>>(x32, w32, dxh, dwh, n8x, n8w);
    }

    cudaFuncSetAttribute(qgemm_hmma_kernel,
                         cudaFuncAttributeMaxDynamicSharedMemorySize, SM_BYTES);
    qgemm_hmma_kernel<<<GRID, THREADS, SM_BYTES, 0>>>(si, sw, bi, out);
}

// round 16
// speedup vs baseline: 1.0307x; 1.0307x over previous
#include <cuda_runtime.h>
#include <cuda_fp16.h>
#include <cstdint>

#define DI __device__ __forceinline__

// Problem shape (fixed by the dataset)
static constexpr int M_TOTAL = 8192;   // B*S = 4*2048
static constexpr int N_TOTAL = 4096;
static constexpr int K_TOTAL = 1024;

// fp16 scratch (harness promotes int8 jax arrays to int32 buffers; int8 values
// are exact in fp16 (11-bit significand), products <= 127*127 exact in the f32
// accumulator, |acc| <= 127*127*1024 < 2^24 -> bit-exact integer GEMM)
__device__ __align__(16) uint16_t g_xh[(size_t)M_TOTAL * K_TOTAL];   // 16 MB
__device__ __align__(16) uint16_t g_wh[(size_t)N_TOTAL * K_TOTAL];   // 8 MB

// Tiling: CTA 128x128, 8 warps (4M x 2N), warp tile 32x64.
// 2 CTAs co-resident per SM: phase-interleaved so one CTA's MMAs cover the
// other's CP_WAIT/__syncthreads/load bubbles.
static constexpr int TILE_M  = 128;
static constexpr int TILE_N  = 128;
static constexpr int KSTAGE  = 64;                   // K elems per stage (128 B/row)
static constexpr int NCHUNK  = K_TOTAL / KSTAGE;     // 16
static constexpr int NSTAGES = 3;
static constexpr int THREADS = 256;                  // 8 warps

// SMEM: fp16 tiles, rows padded 128B -> 144B (9x16B stride => conflict-free ldmatrix)
static constexpr int ROW_B   = 144;
static constexpr int A_STAGE = TILE_M * ROW_B;       // 18432 B
static constexpr int B_STAGE = TILE_N * ROW_B;       // 18432 B
static constexpr int SM_B0   = NSTAGES * A_STAGE;
static constexpr int SM_BYTES = NSTAGES * (A_STAGE + B_STAGE);  // 110592 B (x2 <= 228K)

DI uint32_t smem_u32(const void* p) {
    uint32_t a;
    asm("{ .reg .u64 t; cvta.to.shared.u64 t, %1; cvt.u32.u64 %0, t; }" : "=r"(a) : "l"(p));
    return a;
}
DI void cp16(uint32_t dst, const void* src) {
    asm volatile("cp.async.cg.shared.global [%0], [%1], 16;" :: "r"(dst), "l"(src));
}
#define CP_COMMIT() asm volatile("cp.async.commit_group;" ::: "memory")
#define CP_WAIT1()  asm volatile("cp.async.wait_group 1;" ::: "memory")

#define LDSM4(r0, r1, r2, r3, addr) \
    asm volatile("ldmatrix.sync.aligned.m8n8.x4.shared.b16 {%0,%1,%2,%3}, [%4];" \
                 : "=r"(r0), "=r"(r1), "=r"(r2), "=r"(r3) : "r"(addr))

// HMMA fp16: D(f32) = A(f16,row 16x16) * B(f16,col 16x8) + D
#define MMA_F16(c, a0, a1, a2, a3, b0, b1) \
    asm volatile( \
        "mma.sync.aligned.m16n8k16.row.col.f32.f16.f16.f32 " \
        "{%0,%1,%2,%3}, {%4,%5,%6,%7}, {%8,%9}, {%0,%1,%2,%3};" \
        : "+f"((c)[0]), "+f"((c)[1]), "+f"((c)[2]), "+f"((c)[3]) \
        : "r"(a0), "r"(a1), "r"(a2), "r"(a3), "r"(b0), "r"(b1))

// ---------------- Pack pre-pass: int32 -> fp16, 8 elements/thread ----------------
DI uint32_t f16x2_from_ints(int lo, int hi) {
    __half2 h = __floats2half2_rn((float)lo, (float)hi);   // lo -> .x (low 16 bits)
    return *reinterpret_cast<uint32_t*>(&h);
}
DI uint4 pack8(const int4* p) {
    int4 v0 = p[0], v1 = p[1];
    uint4 o;
    o.x = f16x2_from_ints(v0.x, v0.y);
    o.y = f16x2_from_ints(v0.z, v0.w);
    o.z = f16x2_from_ints(v1.x, v1.y);
    o.w = f16x2_from_ints(v1.z, v1.w);
    return o;
}
__global__ void pack_both(const int4* __restrict__ xs, const int4* __restrict__ ws,
                          uint16_t* __restrict__ xd, uint16_t* __restrict__ wd,
                          int n8x, int n8w) {
    int i = blockIdx.x * blockDim.x + threadIdx.x;
    if (i < n8w) {
        reinterpret_cast<uint4*>(wd)[i] = pack8(ws + (size_t)i * 2);
    } else if (i - n8w < n8x) {
        int j = i - n8w;
        reinterpret_cast<uint4*>(xd)[j] = pack8(xs + (size_t)j * 2);
    }
}

// Load one K-stage: A 128 rows + B 128 rows, 128B/row, via cp.async (4+4 per thread).
DI void load_stage(const uint16_t* __restrict__ x, const uint16_t* __restrict__ w,
                   int m0, int n0, int kc, uint32_t sbase, int stage, int tid) {
    const uint32_t smA = sbase + stage * A_STAGE;
    const uint32_t smB = sbase + SM_B0 + stage * B_STAGE;
    const int k0 = kc * KSTAGE;
#pragma unroll
    for (int i = 0; i < 4; i++) {                    // A: 1024 16B-chunks, 4/thread
        int u = tid + i * THREADS;
        int row = u >> 3, c = u & 7;
        cp16(smA + row * ROW_B + c * 16, x + (size_t)(m0 + row) * K_TOTAL + k0 + c * 8);
    }
#pragma unroll
    for (int i = 0; i < 4; i++) {                    // B: 1024 16B-chunks, 4/thread
        int u = tid + i * THREADS;
        int row = u >> 3, c = u & 7;
        cp16(smB + row * ROW_B + c * 16, w + (size_t)(n0 + row) * K_TOTAL + k0 + c * 8);
    }
}

__global__ void __launch_bounds__(THREADS, 2)
qgemm_hmma_kernel(const float* __restrict__ scale_i, const float* __restrict__ scale_w,
                  const float* __restrict__ bias, float* __restrict__ out) {
    extern __shared__ char smem[];
    const uint16_t* __restrict__ x = g_xh;
    const uint16_t* __restrict__ w = g_wh;
    const uint32_t sbase = smem_u32(smem);
    const int tid = threadIdx.x;
    const int lane = tid & 31;
    const int wid = tid >> 5;
    const int warp_m = wid & 3;        // 4 warps along M: 32 rows each
    const int warp_n = wid >> 2;       // 2 warps along N: 64 cols each
    const int m0 = blockIdx.y * TILE_M;
    const int n0 = blockIdx.x * TILE_N;

    const int tg = lane >> 2;          // groupID (0..7)
    const int tc = lane & 3;           // threadID_in_group

    float acc[2][8][4];
#pragma unroll
    for (int mt = 0; mt < 2; mt++)
#pragma unroll
        for (int nt = 0; nt < 8; nt++)
#pragma unroll
            for (int j = 0; j < 4; j++) acc[mt][nt][j] = 0.0f;

    // ldmatrix lane addressing (within a stage, before k-step offset):
    // A x4: [rows 0-7, k0-7][rows 8-15, k0-7][rows 0-7, k8-15][rows 8-15, k8-15]
    const int am = lane >> 3;
    const uint32_t aOff = (uint32_t)(warp_m * 32 + (am & 1) * 8 + (lane & 7)) * ROW_B
                        + (uint32_t)(am >> 1) * 16;
    // B x4 per n-tile pair p: [n 0-7, k0-7][n 0-7, k8-15][n 8-15, k0-7][n 8-15, k8-15]
    const uint32_t bOff = (uint32_t)(warp_n * 64 + (am >> 1) * 8 + (lane & 7)) * ROW_B
                        + (uint32_t)(am & 1) * 16;

    // Prologue: stages 0,1 in flight
    load_stage(x, w, m0, n0, 0, sbase, 0, tid); CP_COMMIT();
    load_stage(x, w, m0, n0, 1, sbase, 1, tid); CP_COMMIT();

#pragma unroll 1
    for (int kc = 0; kc < NCHUNK; kc++) {
        CP_WAIT1();                    // stage kc resident
        __syncthreads();               // all warps done with stage (kc+2)%3's old data
        if (kc + 2 < NCHUNK)
            load_stage(x, w, m0, n0, kc + 2, sbase, (kc + 2) % NSTAGES, tid);
        CP_COMMIT();

        const int stage = kc % NSTAGES;
        const uint32_t aS = sbase + stage * A_STAGE + aOff;
        const uint32_t bS = sbase + SM_B0 + stage * B_STAGE + bOff;
#pragma unroll
        for (int ks = 0; ks < 4; ks++) {           // four k=16 steps per stage
            const uint32_t ko = ks * 32;           // 16 fp16 = 32 bytes
            uint32_t a00, a01, a02, a03, a10, a11, a12, a13;
            uint32_t e0, e1, e2, e3;               // even-parity B buffer (p=0,2)
            uint32_t o0, o1, o2, o3;               // odd-parity  B buffer (p=1,3)
            LDSM4(a00, a01, a02, a03, aS + ko);
            LDSM4(a10, a11, a12, a13, aS + 16 * ROW_B + ko);
            LDSM4(e0, e1, e2, e3, bS + ko);                       // p=0
            LDSM4(o0, o1, o2, o3, bS + 16 * ROW_B + ko);          // prefetch p=1
            MMA_F16(acc[0][0], a00, a01, a02, a03, e0, e1);       // p=0 consumes even
            MMA_F16(acc[1][0], a10, a11, a12, a13, e0, e1);
            MMA_F16(acc[0][1], a00, a01, a02, a03, e2, e3);
            MMA_F16(acc[1][1], a10, a11, a12, a13, e2, e3);
            LDSM4(e0, e1, e2, e3, bS + 32 * ROW_B + ko);          // prefetch p=2
            MMA_F16(acc[0][2], a00, a01, a02, a03, o0, o1);       // p=1 consumes odd
            MMA_F16(acc[1][2], a10, a11, a12, a13, o0, o1);
            MMA_F16(acc[0][3], a00, a01, a02, a03, o2, o3);
            MMA_F16(acc[1][3], a10, a11, a12, a13, o2, o3);
            LDSM4(o0, o1, o2, o3, bS + 48 * ROW_B + ko);          // prefetch p=3
            MMA_F16(acc[0][4], a00, a01, a02, a03, e0, e1);       // p=2 consumes even
            MMA_F16(acc[1][4], a10, a11, a12, a13, e0, e1);
            MMA_F16(acc[0][5], a00, a01, a02, a03, e2, e3);
            MMA_F16(acc[1][5], a10, a11, a12, a13, e2, e3);
            MMA_F16(acc[0][6], a00, a01, a02, a03, o0, o1);       // p=3 consumes odd
            MMA_F16(acc[1][6], a10, a11, a12, a13, o0, o1);
            MMA_F16(acc[0][7], a00, a01, a02, a03, o2, o3);
            MMA_F16(acc[1][7], a10, a11, a12, a13, o2, o3);
        }
    }

    // Epilogue: out = acc * (scale_i * scale_w[n]) + bias[n]  (acc holds exact integers)
    const float si = __ldg(scale_i);
    const int row0 = m0 + warp_m * 32 + tg;
    const int col0 = n0 + warp_n * 64 + tc * 2;
#pragma unroll
    for (int nt = 0; nt < 8; nt++) {
        const int c = col0 + nt * 8;
        const float2 sw = __ldg(reinterpret_cast<const float2*>(scale_w + c));
        const float2 bb = __ldg(reinterpret_cast<const float2*>(bias + c));
        const float s0 = si * sw.x, s1 = si * sw.y;
#pragma unroll
        for (int mt = 0; mt < 2; mt++) {
            const int r = row0 + mt * 16;
            float2 v0, v1;
            v0.x = fmaf(acc[mt][nt][0], s0, bb.x);
            v0.y = fmaf(acc[mt][nt][1], s1, bb.y);
            v1.x = fmaf(acc[mt][nt][2], s0, bb.x);
            v1.y = fmaf(acc[mt][nt][3], s1, bb.y);
            *reinterpret_cast<float2*>(out + (size_t)r * N_TOTAL + c)       = v0;
            *reinterpret_cast<float2*>(out + (size_t)(r + 8) * N_TOTAL + c) = v1;
        }
    }
}

extern "C" void kernel_launch(void* const* d_in, const int* in_sizes, int n_in,
                              void* d_out, int out_size) {
    // Harness promotes int8 jax arrays to int32 buffers.
    const int4* x32 = (const int4*)d_in[0];      // [8192,1024] int32 (int8 values)
    const int4* w32 = (const int4*)d_in[1];      // [4096,1024] int32
    const float* si = (const float*)d_in[2];     // scalar f32
    const float* sw = (const float*)d_in[3];     // [4096] f32
    const float* bi = (const float*)d_in[4];     // [4096] f32
    float* out = (float*)d_out;                  // [8192,4096] f32

    uint16_t *dxh = nullptr, *dwh = nullptr;
    cudaGetSymbolAddress((void**)&dxh, g_xh);
    cudaGetSymbolAddress((void**)&dwh, g_wh);

    {
        int n8x = (M_TOTAL * K_TOTAL) / 8;       // 1048576
        int n8w = (N_TOTAL * K_TOTAL) / 8;       // 524288
        int total = n8x + n8w;
        pack_both<<<(total + 255) / 256, 256>>>(x32, w32, dxh, dwh, n8x, n8w);
    }

    cudaFuncSetAttribute(qgemm_hmma_kernel,
                         cudaFuncAttributeMaxDynamicSharedMemorySize, SM_BYTES);
    dim3 grid(N_TOTAL / TILE_N, M_TOTAL / TILE_M);  // (32, 64)
    qgemm_hmma_kernel<<<grid, THREADS, SM_BYTES, 0>>>(si, sw, bi, out);
}